// round 5
// baseline (speedup 1.0000x reference)
#include <cuda_runtime.h>
#include <math.h>
#include <stdint.h>

// ---------------------------------------------------------------------------
// Problem constants
// ---------------------------------------------------------------------------
#define BATCH 64
#define PCH   512
#define OCAPS 32
#define ODIM  16
#define ICAPS 4096
#define IDC   8

// ---------------------------------------------------------------------------
// Device scratch (static globals; no runtime allocation)
// ---------------------------------------------------------------------------
__device__ float g_pose[BATCH * ICAPS * IDC];              // 8 MB  squashed pose [b][i][k]
__device__ float g_wT[(size_t)ICAPS * 128 * OCAPS];        // 67 MB W transposed [i][d*8+k][o]
__device__ float g_spart[32 * BATCH * ODIM * OCAPS];       // 4 MB  per-chunk partial s
__device__ float g_s[BATCH * ODIM * OCAPS];                // s     [b][d][o]
__device__ float g_va[BATCH * ODIM * OCAPS];               // v0, then v0+v1
__device__ float g_out[BATCH * ODIM * OCAPS];              // final out capsules [b][d][o]

// ---------------------------------------------------------------------------
// Kernel 1: Conv3x3(SAME) + BN(eval) + ReLU + capsule squash -> g_pose
// grid (4, 64): x = 128-oc block, y = batch. 256 threads.
// smem: image 512*64 f32 (128KB) + weight chunk [128oc][8ci*9] (36KB)
// ---------------------------------------------------------------------------
#define CONV_SMEM ((32768 + 9216) * 4)

__global__ __launch_bounds__(256) void conv_pose_kernel(
    const float* __restrict__ x, const float* __restrict__ cw,
    const float* __restrict__ gamma, const float* __restrict__ beta,
    const float* __restrict__ mean, const float* __restrict__ var)
{
    extern __shared__ float cs[];
    float* img = cs;           // 32768 floats
    float* wts = cs + 32768;   // 9216 floats, layout [oc_local*72 + ci*9 + t]

    const int tid = threadIdx.x;
    const int ocb = blockIdx.x;   // 0..3
    const int b   = blockIdx.y;   // 0..63

    // load full input image for this batch element (coalesced float4)
    {
        const float4* src = (const float4*)(x + (size_t)b * PCH * 64);
        float4* dst = (float4*)img;
        for (int e = tid; e < 8192; e += 256) dst[e] = src[e];
    }

    const int ocg  = tid >> 4;     // 0..15 (8 oc each)
    const int posg = tid & 15;     // 0..15 (2x2 positions each)
    const int ph0  = (posg >> 2) * 2;
    const int pw0  = (posg & 3) * 2;

    float acc[8][4];
#pragma unroll
    for (int j = 0; j < 8; j++)
#pragma unroll
        for (int p = 0; p < 4; p++) acc[j][p] = 0.f;

    // halo masks / safe offsets (independent of cin)
    int   roff[4], coff[4];
    float rm[4], cm[4];
#pragma unroll
    for (int dr = 0; dr < 4; dr++) {
        int r = ph0 - 1 + dr;
        bool v = (r >= 0) && (r < 8);
        rm[dr] = v ? 1.f : 0.f;
        roff[dr] = v ? r * 8 : 0;
    }
#pragma unroll
    for (int dc = 0; dc < 4; dc++) {
        int c = pw0 - 1 + dc;
        bool v = (c >= 0) && (c < 8);
        cm[dc] = v ? 1.f : 0.f;
        coff[dc] = v ? c : 0;
    }

    for (int cc = 0; cc < 64; cc++) {   // 64 chunks of 8 cin
        __syncthreads();
        // stage weights: wts[oc*72 + rr] = conv_w[ocb*128+oc][cc*8..+8][3][3]
        for (int e = tid; e < 9216; e += 256) {
            int oc = e / 72, rr = e - oc * 72;
            wts[e] = cw[(size_t)(ocb * 128 + oc) * 4608 + cc * 72 + rr];
        }
        __syncthreads();

#pragma unroll 1
        for (int ci = 0; ci < 8; ci++) {
            const float* ib = img + (cc * 8 + ci) * 64;
            float xr[4][4];
#pragma unroll
            for (int dr = 0; dr < 4; dr++)
#pragma unroll
                for (int dc = 0; dc < 4; dc++)
                    xr[dr][dc] = rm[dr] * cm[dc] * ib[roff[dr] + coff[dc]];

            const float* wb = wts + (ocg * 8) * 72 + ci * 9;
#pragma unroll
            for (int j = 0; j < 8; j++) {
                float w0 = wb[j*72+0], w1 = wb[j*72+1], w2 = wb[j*72+2];
                float w3 = wb[j*72+3], w4 = wb[j*72+4], w5 = wb[j*72+5];
                float w6 = wb[j*72+6], w7 = wb[j*72+7], w8 = wb[j*72+8];
#pragma unroll
                for (int pr = 0; pr < 2; pr++)
#pragma unroll
                    for (int pc = 0; pc < 2; pc++) {
                        float a = acc[j][pr * 2 + pc];
                        a = fmaf(w0, xr[pr+0][pc+0], a);
                        a = fmaf(w1, xr[pr+0][pc+1], a);
                        a = fmaf(w2, xr[pr+0][pc+2], a);
                        a = fmaf(w3, xr[pr+1][pc+0], a);
                        a = fmaf(w4, xr[pr+1][pc+1], a);
                        a = fmaf(w5, xr[pr+1][pc+2], a);
                        a = fmaf(w6, xr[pr+2][pc+0], a);
                        a = fmaf(w7, xr[pr+2][pc+1], a);
                        a = fmaf(w8, xr[pr+2][pc+2], a);
                        acc[j][pr * 2 + pc] = a;
                    }
            }
        }
    }

    // epilogue: BN + ReLU + squash over the thread's 8-channel capsule group
    float sc[8], sh[8];
#pragma unroll
    for (int j = 0; j < 8; j++) {
        int oc = ocb * 128 + ocg * 8 + j;
        float inv = gamma[oc] * rsqrtf(var[oc] + 1e-5f);
        sc[j] = inv;
        sh[j] = beta[oc] - mean[oc] * inv;
    }
    const int g = ocb * 16 + ocg;   // capsule group index 0..63
#pragma unroll
    for (int p = 0; p < 4; p++) {
        int pos = (ph0 + (p >> 1)) * 8 + (pw0 + (p & 1));
        float y[8];
        float ms = 0.f;
#pragma unroll
        for (int j = 0; j < 8; j++) {
            float v = fmaf(acc[j][p], sc[j], sh[j]);
            v = fmaxf(v, 0.f);
            y[j] = v;
            ms = fmaf(v, v, ms);
        }
        float scale = ms / ((1.f + ms) * (sqrtf(ms) + 1e-8f));
        float* dst = g_pose + ((size_t)b * ICAPS + g * 64 + pos) * 8;
        float4 lo = make_float4(y[0]*scale, y[1]*scale, y[2]*scale, y[3]*scale);
        float4 hi = make_float4(y[4]*scale, y[5]*scale, y[6]*scale, y[7]*scale);
        ((float4*)dst)[0] = lo;
        ((float4*)dst)[1] = hi;
    }
}

// ---------------------------------------------------------------------------
// Kernel 2: transpose caps_w [O][I][128] -> g_wT [I][128][O] (coalesced both sides)
// grid 4096 (one block per i), 256 threads. smem tile [32 o][129] padded.
// ---------------------------------------------------------------------------
__global__ __launch_bounds__(256) void transpose_w_kernel(const float* __restrict__ W)
{
    __shared__ float t[32 * 129];
    const int tid = threadIdx.x;
    const int i = blockIdx.x;
    for (int e = tid; e < 4096; e += 256) {
        int o = e >> 7, q = e & 127;
        t[o * 129 + q] = W[((size_t)o * ICAPS + i) * 128 + q];
    }
    __syncthreads();
    for (int e = tid; e < 4096; e += 256) {
        int q = e >> 5, o = e & 31;
        g_wT[((size_t)i * 128 + q) * 32 + o] = t[o * 129 + q];
    }
}

// ---------------------------------------------------------------------------
// Kernel 3: one routing pass. Recomputes x_hat on the fly; W in registers
// per (lane=o, i), reused across 8 batch elements. lane = output capsule ->
// softmax over o is a pure warp shuffle.
// grid (32, 8): x = i-chunk (128 i's), y = batch group (8 b). 256 thr = 8 warps.
// UNIFORM: c = 1/32 (iter 0). Otherwise logit = g_va . x_hat (g_va = v0 or v0+v1).
// smem: pose 32KB + v 16KB + per-warp s-partials 128KB = 176KB
// ---------------------------------------------------------------------------
#define ROUT_SMEM (45056 * 4)

template <bool UNIFORM>
__global__ __launch_bounds__(256, 1) void routing_kernel()
{
    extern __shared__ float rs[];
    float* pose_s = rs;           // [8 b][128 i][8 k]          = 8192
    float* v_s    = rs + 8192;    // [8 b][16 d][32 o]          = 4096
    float* sacc   = rs + 12288;   // [8 w][8 b][16 d][32 o]     = 32768

    const int tid   = threadIdx.x;
    const int warp  = tid >> 5;
    const int lane  = tid & 31;     // = o
    const int chunk = blockIdx.x;   // 0..31
    const int bg    = blockIdx.y;   // 0..7

    for (int e = tid; e < 32768; e += 256) sacc[e] = 0.f;
    for (int e = tid; e < 8192; e += 256) {
        int bb = e >> 10, r = e & 1023;
        pose_s[e] = g_pose[((size_t)(bg * 8 + bb) * ICAPS + chunk * 128) * 8 + r];
    }
    if (!UNIFORM) {
        for (int e = tid; e < 4096; e += 256) v_s[e] = g_va[bg * 4096 + e];
    }
    __syncthreads();

#pragma unroll 1
    for (int t = 0; t < 16; t++) {
        const int li = t * 8 + warp;
        const int i  = chunk * 128 + li;
        // W'[i, q=d*8+k, o=lane] : 128 coalesced loads into registers
        const float* wp = g_wT + (size_t)i * 4096 + lane;
        float wreg[128];
#pragma unroll
        for (int q = 0; q < 128; q++) wreg[q] = __ldg(wp + q * 32);

#pragma unroll 1
        for (int bb = 0; bb < 8; bb++) {
            const float* pp = pose_s + (bb * 128 + li) * 8;
            float p0 = pp[0], p1 = pp[1], p2 = pp[2], p3 = pp[3];
            float p4 = pp[4], p5 = pp[5], p6 = pp[6], p7 = pp[7];

            float xh[16];
#pragma unroll
            for (int d = 0; d < 16; d++) {
                float v = wreg[d * 8 + 0] * p0;
                v = fmaf(wreg[d * 8 + 1], p1, v);
                v = fmaf(wreg[d * 8 + 2], p2, v);
                v = fmaf(wreg[d * 8 + 3], p3, v);
                v = fmaf(wreg[d * 8 + 4], p4, v);
                v = fmaf(wreg[d * 8 + 5], p5, v);
                v = fmaf(wreg[d * 8 + 6], p6, v);
                v = fmaf(wreg[d * 8 + 7], p7, v);
                xh[d] = v;
            }

            float c;
            if (UNIFORM) {
                c = 0.03125f;
            } else {
                float lg = 0.f;
#pragma unroll
                for (int d = 0; d < 16; d++)
                    lg = fmaf(v_s[(bb * 16 + d) * 32 + lane], xh[d], lg);
                float m = lg;
#pragma unroll
                for (int off = 16; off > 0; off >>= 1)
                    m = fmaxf(m, __shfl_xor_sync(0xffffffffu, m, off));
                float ex = __expf(lg - m);
                float sm = ex;
#pragma unroll
                for (int off = 16; off > 0; off >>= 1)
                    sm += __shfl_xor_sync(0xffffffffu, sm, off);
                c = ex / sm;
            }

            float* sb = sacc + ((warp * 8 + bb) * 16) * 32 + lane;
#pragma unroll
            for (int d = 0; d < 16; d++)
                sb[d * 32] = fmaf(c, xh[d], sb[d * 32]);
        }
    }

    __syncthreads();
    // deterministic per-chunk partial (no atomics)
    for (int e = tid; e < 4096; e += 256) {
        float s = 0.f;
#pragma unroll
        for (int w = 0; w < 8; w++) s += sacc[w * 4096 + e];
        g_spart[(size_t)chunk * 32768 + bg * 4096 + e] = s;
    }
}

// ---------------------------------------------------------------------------
// Kernel 4: reduce 32 chunk-partials -> g_s   (fixed order = deterministic)
// ---------------------------------------------------------------------------
__global__ void reduce_s_kernel()
{
    int e = blockIdx.x * 256 + threadIdx.x;   // 32768 total
    float s = 0.f;
#pragma unroll
    for (int c = 0; c < 32; c++) s += g_spart[(size_t)c * 32768 + e];
    g_s[e] = s;
}

// ---------------------------------------------------------------------------
// Kernel 5: squash s -> v.   MODE 0: g_va = v0.  MODE 1: g_va += v1 (=v0+v1).
// MODE 2: g_out = squash(s2).  grid 64, block 32 (lane = o).
// ---------------------------------------------------------------------------
template <int MODE>
__global__ void squash_out_kernel()
{
    const int b = blockIdx.x, o = threadIdx.x;
    float s[16], ms = 0.f;
#pragma unroll
    for (int d = 0; d < 16; d++) {
        s[d] = g_s[(b * 16 + d) * 32 + o];
        ms = fmaf(s[d], s[d], ms);
    }
    float scale = ms / ((1.f + ms) * (sqrtf(ms) + 1e-8f));
#pragma unroll
    for (int d = 0; d < 16; d++) {
        int idx = (b * 16 + d) * 32 + o;
        float v = s[d] * scale;
        if (MODE == 0) g_va[idx] = v;
        else if (MODE == 1) g_va[idx] += v;
        else g_out[idx] = v;
    }
}

// ---------------------------------------------------------------------------
// Kernel 6: VAE head.  out[b,o,:16] -> h[1024] (relu) -> z_mu[64]; z_var head.
// grid 256 blocks x 256 threads; 8 (b,o) pairs per block, h tile in smem.
// Writes z (=z_mu), z_mu, z_var at offsets 0 / 131072 / 262144.
// ---------------------------------------------------------------------------
__global__ __launch_bounds__(256) void head_kernel(
    const float* __restrict__ W1, const float* __restrict__ B1,
    const float* __restrict__ W2, const float* __restrict__ B2,
    const float* __restrict__ Wv, const float* __restrict__ Bv,
    float* __restrict__ out)
{
    __shared__ float ov[8][16];
    __shared__ float hb[8][1024];
    const int tid = threadIdx.x;
    const int pid0 = blockIdx.x * 8;

    if (tid < 128) {
        int pr = tid >> 4, d = tid & 15;
        int pid = pid0 + pr, b = pid >> 5, o = pid & 31;
        ov[pr][d] = g_out[(b * 16 + d) * 32 + o];
    }
    __syncthreads();

    for (int idx = tid; idx < 8192; idx += 256) {
        int pr = idx >> 10, j = idx & 1023;
        float a = B1[j];
#pragma unroll
        for (int k = 0; k < 16; k++)
            a = fmaf(ov[pr][k], W1[k * 1024 + j], a);
        hb[pr][j] = fmaxf(a, 0.f);
    }
    __syncthreads();

#pragma unroll 1
    for (int rep = 0; rep < 2; rep++) {
        int dotid = rep * 256 + tid;      // 0..511
        int pr = dotid >> 6, c = dotid & 63;
        float a = B2[c];
#pragma unroll 8
        for (int j = 0; j < 1024; j++)
            a = fmaf(hb[pr][j], W2[j * 64 + c], a);
        int pid = pid0 + pr;
        out[pid * 64 + c] = a;                 // z (= z_mu in eval)
        out[131072 + pid * 64 + c] = a;        // z_mu

        float av = Bv[c];
#pragma unroll
        for (int k = 0; k < 16; k++)
            av = fmaf(ov[pr][k], Wv[k * 64 + c], av);
        float sp = fmaxf(av, 0.f) + log1pf(expf(-fabsf(av)));
        out[262144 + pid * 64 + c] = sp + 1e-8f;  // z_var
    }
}

// ---------------------------------------------------------------------------
// Launch
// ---------------------------------------------------------------------------
extern "C" void kernel_launch(void* const* d_in, const int* in_sizes, int n_in,
                              void* d_out, int out_size)
{
    (void)in_sizes; (void)n_in; (void)out_size;
    const float* x      = (const float*)d_in[0];
    const float* conv_w = (const float*)d_in[1];
    const float* gam    = (const float*)d_in[2];
    const float* bet    = (const float*)d_in[3];
    const float* mu     = (const float*)d_in[4];
    const float* var    = (const float*)d_in[5];
    const float* capw   = (const float*)d_in[6];
    const float* w1     = (const float*)d_in[7];
    const float* b1     = (const float*)d_in[8];
    const float* w2     = (const float*)d_in[9];
    const float* b2     = (const float*)d_in[10];
    const float* wv     = (const float*)d_in[11];
    const float* bv     = (const float*)d_in[12];
    float* out = (float*)d_out;

    cudaFuncSetAttribute(conv_pose_kernel,
                         cudaFuncAttributeMaxDynamicSharedMemorySize, CONV_SMEM);
    cudaFuncSetAttribute(routing_kernel<true>,
                         cudaFuncAttributeMaxDynamicSharedMemorySize, ROUT_SMEM);
    cudaFuncSetAttribute(routing_kernel<false>,
                         cudaFuncAttributeMaxDynamicSharedMemorySize, ROUT_SMEM);

    conv_pose_kernel<<<dim3(4, 64), 256, CONV_SMEM>>>(x, conv_w, gam, bet, mu, var);
    transpose_w_kernel<<<4096, 256>>>(capw);

    // pass 0: c = 1/32
    routing_kernel<true><<<dim3(32, 8), 256, ROUT_SMEM>>>();
    reduce_s_kernel<<<128, 256>>>();
    squash_out_kernel<0><<<64, 32>>>();

    // pass 1: logits = v0 . x_hat
    routing_kernel<false><<<dim3(32, 8), 256, ROUT_SMEM>>>();
    reduce_s_kernel<<<128, 256>>>();
    squash_out_kernel<1><<<64, 32>>>();      // g_va = v0 + v1

    // pass 2: logits = (v0 + v1) . x_hat
    routing_kernel<false><<<dim3(32, 8), 256, ROUT_SMEM>>>();
    reduce_s_kernel<<<128, 256>>>();
    squash_out_kernel<2><<<64, 32>>>();

    head_kernel<<<256, 256>>>(w1, b1, w2, b2, wv, bv, out);
}

// round 8
// speedup vs baseline: 1.4892x; 1.4892x over previous
#include <cuda_runtime.h>
#include <math.h>
#include <stdint.h>

typedef unsigned long long u64;

// ---------------------------------------------------------------------------
// Problem constants
// ---------------------------------------------------------------------------
#define BATCH 64
#define PCH   512
#define OCAPS 32
#define ODIM  16
#define ICAPS 4096
#define IDC   8

// ---------------------------------------------------------------------------
// Device scratch
// ---------------------------------------------------------------------------
__device__ float g_pose[BATCH * ICAPS * IDC];              // 8 MB  squashed pose [b][i][k]
__device__ float g_cwT[4608 * 512];                        // 9.4MB conv_w transposed [cin*9+t][oc]
__device__ float g_wT[(size_t)ICAPS * 128 * OCAPS];        // 67 MB caps_w transposed [i][d*8+k][o]
__device__ float g_spart[32 * BATCH * ODIM * OCAPS];       // 4 MB  per-chunk partial s
__device__ float g_s[BATCH * ODIM * OCAPS];
__device__ float g_va[BATCH * ODIM * OCAPS];
__device__ float g_out[BATCH * ODIM * OCAPS];

// ---------------------------------------------------------------------------
// f32x2 helpers (sm_103a packed fp32 pipe)
// ---------------------------------------------------------------------------
__device__ __forceinline__ u64 pack2(float lo, float hi) {
    u64 r; asm("mov.b64 %0, {%1, %2};" : "=l"(r) : "f"(lo), "f"(hi)); return r;
}
__device__ __forceinline__ void fma2(u64& d, u64 a, u64 b) {
    asm("fma.rn.f32x2 %0, %1, %2, %0;" : "+l"(d) : "l"(a), "l"(b));
}
__device__ __forceinline__ float2 unpack2(u64 v) {
    float2 f; asm("mov.b64 {%0, %1}, %2;" : "=f"(f.x), "=f"(f.y) : "l"(v)); return f;
}

// ---------------------------------------------------------------------------
// Kernel 0: transpose conv_w [oc][cin*9] -> g_cwT [cin*9][oc]
// grid (144, 16): 32 rr x 32 oc tiles. 256 threads.
// ---------------------------------------------------------------------------
__global__ __launch_bounds__(256) void transpose_cw_kernel(const float* __restrict__ cw)
{
    __shared__ float t[32 * 33];
    const int tid = threadIdx.x;
    const int rrb = blockIdx.x;   // 0..143 (32 rr each, 4608 total)
    const int ocb = blockIdx.y;   // 0..15  (32 oc each)
    for (int e = tid; e < 1024; e += 256) {
        int ocl = e >> 5, rr = e & 31;
        t[ocl * 33 + rr] = cw[(size_t)(ocb * 32 + ocl) * 4608 + rrb * 32 + rr];
    }
    __syncthreads();
    for (int e = tid; e < 1024; e += 256) {
        int rr = e >> 5, ocl = e & 31;
        g_cwT[(size_t)(rrb * 32 + rr) * 512 + ocb * 32 + ocl] = t[ocl * 33 + rr];
    }
}

// ---------------------------------------------------------------------------
// Profiler-slot pad (empty; steers ncu's fixed -s onto the conv kernel)
// ---------------------------------------------------------------------------
__global__ void prof_pad_kernel() {}

// ---------------------------------------------------------------------------
// Kernel 1: Conv3x3(SAME) + BN(eval) + ReLU + capsule squash -> g_pose
// grid (16, 64): x = 32-oc block, y = batch. 256 threads = 8 warps.
// warp = 4 consecutive oc (2 f32x2 pairs); lane = 2 adjacent positions.
// smem: img chunk 512 + w chunk 2304 floats = 11.3 KB  -> high occupancy.
// ---------------------------------------------------------------------------
#define CONV_SMEM (2816 * 4)

__global__ __launch_bounds__(256) void conv_pose_kernel(
    const float* __restrict__ x,
    const float* __restrict__ gamma, const float* __restrict__ beta,
    const float* __restrict__ mean, const float* __restrict__ var)
{
    extern __shared__ float cs[];
    float* img = cs;          // [8 ci][64 pos]
    float* wts = cs + 512;    // [8 ci][9 tap][32 oc]

    const int tid  = threadIdx.x;
    const int warp = tid >> 5;        // 0..7 -> 4 oc
    const int lane = tid & 31;
    const int ocb  = blockIdx.x;      // 0..15
    const int b    = blockIdx.y;      // 0..63

    const int r  = lane >> 2;         // row 0..7
    const int c0 = (lane & 3) * 2;    // col pair base 0,2,4,6

    // halo masks / offsets: rows r-1..r+1, cols c0-1..c0+2
    float m[3][4];
    int   off[3][4];
#pragma unroll
    for (int dr = 0; dr < 3; dr++) {
        int rr = r - 1 + dr;
        bool rv = (rr >= 0) && (rr < 8);
#pragma unroll
        for (int dc = 0; dc < 4; dc++) {
            int ccc = c0 - 1 + dc;
            bool cv = (ccc >= 0) && (ccc < 8);
            m[dr][dc] = (rv && cv) ? 1.f : 0.f;
            off[dr][dc] = (rv ? rr * 8 : 0) + (cv ? ccc : 0);
        }
    }

    u64 acc[2][2];
    acc[0][0] = acc[0][1] = acc[1][0] = acc[1][1] = 0ull;   // {0.f,0.f}

    for (int cc = 0; cc < 64; cc++) {
        __syncthreads();
        for (int e = tid; e < 512; e += 256)
            img[e] = x[(size_t)b * 32768 + cc * 512 + e];
        for (int e = tid; e < 2304; e += 256)
            wts[e] = g_cwT[(size_t)(cc * 72 + (e >> 5)) * 512 + ocb * 32 + (e & 31)];
        __syncthreads();

#pragma unroll
        for (int ci = 0; ci < 8; ci++) {
            const float* ib = img + ci * 64;
            u64 xp[3][4];
#pragma unroll
            for (int dr = 0; dr < 3; dr++)
#pragma unroll
                for (int dc = 0; dc < 4; dc++) {
                    float v = m[dr][dc] * ib[off[dr][dc]];
                    xp[dr][dc] = pack2(v, v);
                }

            const float* wb = wts + ci * 288 + warp * 4;
#pragma unroll
            for (int t = 0; t < 9; t++) {
                u64 w0 = *(const u64*)(wb + t * 32);      // oc pair 0
                u64 w1 = *(const u64*)(wb + t * 32 + 2);  // oc pair 1
                const int th = t / 3, tw = t % 3;
                fma2(acc[0][0], w0, xp[th][tw]);
                fma2(acc[0][1], w0, xp[th][tw + 1]);
                fma2(acc[1][0], w1, xp[th][tw]);
                fma2(acc[1][1], w1, xp[th][tw + 1]);
            }
        }
    }

    // ---- epilogue: BN + ReLU, cross-warp capsule squash via smem ----
    __syncthreads();
    float* ybuf = cs;          // [64 pos][32 oc]
    float* sq   = cs + 2048;   // [64 pos][8 warp]

    const int oc0 = ocb * 32 + warp * 4;
    float scl[4], shf[4];
#pragma unroll
    for (int j = 0; j < 4; j++) {
        float inv = gamma[oc0 + j] * rsqrtf(var[oc0 + j] + 1e-5f);
        scl[j] = inv;
        shf[j] = beta[oc0 + j] - mean[oc0 + j] * inv;
    }

#pragma unroll
    for (int pc = 0; pc < 2; pc++) {
        int pos = r * 8 + c0 + pc;
        float ss = 0.f;
#pragma unroll
        for (int pr = 0; pr < 2; pr++) {
            float2 f = unpack2(acc[pr][pc]);
            float y0 = fmaxf(fmaf(f.x, scl[pr * 2 + 0], shf[pr * 2 + 0]), 0.f);
            float y1 = fmaxf(fmaf(f.y, scl[pr * 2 + 1], shf[pr * 2 + 1]), 0.f);
            ybuf[pos * 32 + warp * 4 + pr * 2 + 0] = y0;
            ybuf[pos * 32 + warp * 4 + pr * 2 + 1] = y1;
            ss = fmaf(y0, y0, fmaf(y1, y1, ss));
        }
        sq[pos * 8 + warp] = ss;
    }
    __syncthreads();

    // 256 threads -> (64 pos) x (4 capsule groups of 8 oc)
    {
        int pos = tid >> 2, g = tid & 3;
        float ms = sq[pos * 8 + g * 2] + sq[pos * 8 + g * 2 + 1];
        float scale = ms / ((1.f + ms) * (sqrtf(ms) + 1e-8f));
        const float* src = ybuf + pos * 32 + g * 8;
        float* dst = g_pose + ((size_t)b * ICAPS + (ocb * 4 + g) * 64 + pos) * 8;
        float4 lo = make_float4(src[0]*scale, src[1]*scale, src[2]*scale, src[3]*scale);
        float4 hi = make_float4(src[4]*scale, src[5]*scale, src[6]*scale, src[7]*scale);
        ((float4*)dst)[0] = lo;
        ((float4*)dst)[1] = hi;
    }
}

// ---------------------------------------------------------------------------
// Kernel 2: transpose caps_w [O][I][128] -> g_wT [I][128][O]
// ---------------------------------------------------------------------------
__global__ __launch_bounds__(256) void transpose_w_kernel(const float* __restrict__ W)
{
    __shared__ float t[32 * 129];
    const int tid = threadIdx.x;
    const int i = blockIdx.x;
    for (int e = tid; e < 4096; e += 256) {
        int o = e >> 7, q = e & 127;
        t[o * 129 + q] = W[((size_t)o * ICAPS + i) * 128 + q];
    }
    __syncthreads();
    for (int e = tid; e < 4096; e += 256) {
        int q = e >> 5, o = e & 31;
        g_wT[((size_t)i * 128 + q) * 32 + o] = t[o * 129 + q];
    }
}

// ---------------------------------------------------------------------------
// Kernel 3: routing pass (unchanged from passing R4 version)
// ---------------------------------------------------------------------------
#define ROUT_SMEM (45056 * 4)

template <bool UNIFORM>
__global__ __launch_bounds__(256, 1) void routing_kernel()
{
    extern __shared__ float rs[];
    float* pose_s = rs;           // [8 b][128 i][8 k]
    float* v_s    = rs + 8192;    // [8 b][16 d][32 o]
    float* sacc   = rs + 12288;   // [8 w][8 b][16 d][32 o]

    const int tid   = threadIdx.x;
    const int warp  = tid >> 5;
    const int lane  = tid & 31;     // = o
    const int chunk = blockIdx.x;   // 0..31
    const int bg    = blockIdx.y;   // 0..7

    for (int e = tid; e < 32768; e += 256) sacc[e] = 0.f;
    for (int e = tid; e < 8192; e += 256) {
        int bb = e >> 10, r = e & 1023;
        pose_s[e] = g_pose[((size_t)(bg * 8 + bb) * ICAPS + chunk * 128) * 8 + r];
    }
    if (!UNIFORM) {
        for (int e = tid; e < 4096; e += 256) v_s[e] = g_va[bg * 4096 + e];
    }
    __syncthreads();

#pragma unroll 1
    for (int t = 0; t < 16; t++) {
        const int li = t * 8 + warp;
        const int i  = chunk * 128 + li;
        const float* wp = g_wT + (size_t)i * 4096 + lane;
        float wreg[128];
#pragma unroll
        for (int q = 0; q < 128; q++) wreg[q] = __ldg(wp + q * 32);

#pragma unroll 1
        for (int bb = 0; bb < 8; bb++) {
            const float* pp = pose_s + (bb * 128 + li) * 8;
            float p0 = pp[0], p1 = pp[1], p2 = pp[2], p3 = pp[3];
            float p4 = pp[4], p5 = pp[5], p6 = pp[6], p7 = pp[7];

            float xh[16];
#pragma unroll
            for (int d = 0; d < 16; d++) {
                float v = wreg[d * 8 + 0] * p0;
                v = fmaf(wreg[d * 8 + 1], p1, v);
                v = fmaf(wreg[d * 8 + 2], p2, v);
                v = fmaf(wreg[d * 8 + 3], p3, v);
                v = fmaf(wreg[d * 8 + 4], p4, v);
                v = fmaf(wreg[d * 8 + 5], p5, v);
                v = fmaf(wreg[d * 8 + 6], p6, v);
                v = fmaf(wreg[d * 8 + 7], p7, v);
                xh[d] = v;
            }

            float c;
            if (UNIFORM) {
                c = 0.03125f;
            } else {
                float lg = 0.f;
#pragma unroll
                for (int d = 0; d < 16; d++)
                    lg = fmaf(v_s[(bb * 16 + d) * 32 + lane], xh[d], lg);
                float mx = lg;
#pragma unroll
                for (int o2 = 16; o2 > 0; o2 >>= 1)
                    mx = fmaxf(mx, __shfl_xor_sync(0xffffffffu, mx, o2));
                float ex = __expf(lg - mx);
                float sm = ex;
#pragma unroll
                for (int o2 = 16; o2 > 0; o2 >>= 1)
                    sm += __shfl_xor_sync(0xffffffffu, sm, o2);
                c = ex / sm;
            }

            float* sb = sacc + ((warp * 8 + bb) * 16) * 32 + lane;
#pragma unroll
            for (int d = 0; d < 16; d++)
                sb[d * 32] = fmaf(c, xh[d], sb[d * 32]);
        }
    }

    __syncthreads();
    for (int e = tid; e < 4096; e += 256) {
        float s = 0.f;
#pragma unroll
        for (int w = 0; w < 8; w++) s += sacc[w * 4096 + e];
        g_spart[(size_t)chunk * 32768 + bg * 4096 + e] = s;
    }
}

// ---------------------------------------------------------------------------
// Kernel 4: reduce 32 chunk-partials -> g_s
// ---------------------------------------------------------------------------
__global__ void reduce_s_kernel()
{
    int e = blockIdx.x * 256 + threadIdx.x;
    float s = 0.f;
#pragma unroll
    for (int c = 0; c < 32; c++) s += g_spart[(size_t)c * 32768 + e];
    g_s[e] = s;
}

// ---------------------------------------------------------------------------
// Kernel 5: squash s -> v
// ---------------------------------------------------------------------------
template <int MODE>
__global__ void squash_out_kernel()
{
    const int b = blockIdx.x, o = threadIdx.x;
    float s[16], ms = 0.f;
#pragma unroll
    for (int d = 0; d < 16; d++) {
        s[d] = g_s[(b * 16 + d) * 32 + o];
        ms = fmaf(s[d], s[d], ms);
    }
    float scale = ms / ((1.f + ms) * (sqrtf(ms) + 1e-8f));
#pragma unroll
    for (int d = 0; d < 16; d++) {
        int idx = (b * 16 + d) * 32 + o;
        float v = s[d] * scale;
        if (MODE == 0) g_va[idx] = v;
        else if (MODE == 1) g_va[idx] += v;
        else g_out[idx] = v;
    }
}

// ---------------------------------------------------------------------------
// Kernel 6: VAE head
// ---------------------------------------------------------------------------
__global__ __launch_bounds__(256) void head_kernel(
    const float* __restrict__ W1, const float* __restrict__ B1,
    const float* __restrict__ W2, const float* __restrict__ B2,
    const float* __restrict__ Wv, const float* __restrict__ Bv,
    float* __restrict__ out)
{
    __shared__ float ov[8][16];
    __shared__ float hb[8][1024];
    const int tid = threadIdx.x;
    const int pid0 = blockIdx.x * 8;

    if (tid < 128) {
        int pr = tid >> 4, d = tid & 15;
        int pid = pid0 + pr, b = pid >> 5, o = pid & 31;
        ov[pr][d] = g_out[(b * 16 + d) * 32 + o];
    }
    __syncthreads();

    for (int idx = tid; idx < 8192; idx += 256) {
        int pr = idx >> 10, j = idx & 1023;
        float a = B1[j];
#pragma unroll
        for (int k = 0; k < 16; k++)
            a = fmaf(ov[pr][k], W1[k * 1024 + j], a);
        hb[pr][j] = fmaxf(a, 0.f);
    }
    __syncthreads();

#pragma unroll 1
    for (int rep = 0; rep < 2; rep++) {
        int dotid = rep * 256 + tid;
        int pr = dotid >> 6, c = dotid & 63;
        float a = B2[c];
#pragma unroll 8
        for (int j = 0; j < 1024; j++)
            a = fmaf(hb[pr][j], W2[j * 64 + c], a);
        int pid = pid0 + pr;
        out[pid * 64 + c] = a;
        out[131072 + pid * 64 + c] = a;

        float av = Bv[c];
#pragma unroll
        for (int k = 0; k < 16; k++)
            av = fmaf(ov[pr][k], Wv[k * 64 + c], av);
        float sp = fmaxf(av, 0.f) + log1pf(expf(-fabsf(av)));
        out[262144 + pid * 64 + c] = sp + 1e-8f;
    }
}

// ---------------------------------------------------------------------------
// Launch
// ---------------------------------------------------------------------------
extern "C" void kernel_launch(void* const* d_in, const int* in_sizes, int n_in,
                              void* d_out, int out_size)
{
    (void)in_sizes; (void)n_in; (void)out_size;
    const float* x      = (const float*)d_in[0];
    const float* conv_w = (const float*)d_in[1];
    const float* gam    = (const float*)d_in[2];
    const float* bet    = (const float*)d_in[3];
    const float* mu     = (const float*)d_in[4];
    const float* var    = (const float*)d_in[5];
    const float* capw   = (const float*)d_in[6];
    const float* w1     = (const float*)d_in[7];
    const float* b1     = (const float*)d_in[8];
    const float* w2     = (const float*)d_in[9];
    const float* b2     = (const float*)d_in[10];
    const float* wv     = (const float*)d_in[11];
    const float* bv     = (const float*)d_in[12];
    float* out = (float*)d_out;

    cudaFuncSetAttribute(routing_kernel<true>,
                         cudaFuncAttributeMaxDynamicSharedMemorySize, ROUT_SMEM);
    cudaFuncSetAttribute(routing_kernel<false>,
                         cudaFuncAttributeMaxDynamicSharedMemorySize, ROUT_SMEM);

    // order chosen so my launch index 3 (= profiled slot) is the conv kernel
    transpose_cw_kernel<<<dim3(144, 16), 256>>>(conv_w);          // 0
    transpose_w_kernel<<<4096, 256>>>(capw);                      // 1
    prof_pad_kernel<<<1, 32>>>();                                 // 2
    conv_pose_kernel<<<dim3(16, 64), 256, CONV_SMEM>>>(x, gam, bet, mu, var); // 3

    routing_kernel<true><<<dim3(32, 8), 256, ROUT_SMEM>>>();      // 4
    reduce_s_kernel<<<128, 256>>>();
    squash_out_kernel<0><<<64, 32>>>();

    routing_kernel<false><<<dim3(32, 8), 256, ROUT_SMEM>>>();
    reduce_s_kernel<<<128, 256>>>();
    squash_out_kernel<1><<<64, 32>>>();

    routing_kernel<false><<<dim3(32, 8), 256, ROUT_SMEM>>>();
    reduce_s_kernel<<<128, 256>>>();
    squash_out_kernel<2><<<64, 32>>>();

    head_kernel<<<256, 256>>>(w1, b1, w2, b2, wv, bv, out);
}

// round 9
// speedup vs baseline: 1.5456x; 1.0378x over previous
#include <cuda_runtime.h>
#include <math.h>
#include <stdint.h>

typedef unsigned long long u64;

// ---------------------------------------------------------------------------
// Problem constants
// ---------------------------------------------------------------------------
#define BATCH 64
#define PCH   512
#define OCAPS 32
#define ODIM  16
#define ICAPS 4096
#define IDC   8

// ---------------------------------------------------------------------------
// Device scratch
// ---------------------------------------------------------------------------
__device__ float g_pose[BATCH * ICAPS * IDC];              // 8 MB  squashed pose [b][i][k]
__device__ float g_cwT[4608 * 512];                        // 9.4MB conv_w transposed [cin*9+t][oc]
__device__ u64   g_wT2[(size_t)ICAPS * 2048];              // 67 MB caps_w packed [i][k*8+d2][o] = {W[o][i][2d2][k], W[o][i][2d2+1][k]}
__device__ float g_spart[32 * BATCH * ODIM * OCAPS];       // 4 MB  per-chunk partial s
__device__ float g_va[BATCH * ODIM * OCAPS];               // v0, then v0+v1
__device__ float g_out[BATCH * ODIM * OCAPS];              // final out capsules [b][d][o]

// ---------------------------------------------------------------------------
// f32x2 helpers
// ---------------------------------------------------------------------------
__device__ __forceinline__ u64 pack2(float lo, float hi) {
    u64 r; asm("mov.b64 %0, {%1, %2};" : "=l"(r) : "f"(lo), "f"(hi)); return r;
}
__device__ __forceinline__ void fma2(u64& d, u64 a, u64 b) {
    asm("fma.rn.f32x2 %0, %1, %2, %0;" : "+l"(d) : "l"(a), "l"(b));
}
__device__ __forceinline__ float2 unpack2(u64 v) {
    float2 f; asm("mov.b64 {%0, %1}, %2;" : "=f"(f.x), "=f"(f.y) : "l"(v)); return f;
}

// ---------------------------------------------------------------------------
// Kernel 0: transpose conv_w [oc][cin*9] -> g_cwT [cin*9][oc]
// ---------------------------------------------------------------------------
__global__ __launch_bounds__(256) void transpose_cw_kernel(const float* __restrict__ cw)
{
    __shared__ float t[32 * 33];
    const int tid = threadIdx.x;
    const int rrb = blockIdx.x;   // 0..143
    const int ocb = blockIdx.y;   // 0..15
    for (int e = tid; e < 1024; e += 256) {
        int ocl = e >> 5, rr = e & 31;
        t[ocl * 33 + rr] = cw[(size_t)(ocb * 32 + ocl) * 4608 + rrb * 32 + rr];
    }
    __syncthreads();
    for (int e = tid; e < 1024; e += 256) {
        int rr = e >> 5, ocl = e & 31;
        g_cwT[(size_t)(rrb * 32 + rr) * 512 + ocb * 32 + ocl] = t[ocl * 33 + rr];
    }
}

// ---------------------------------------------------------------------------
// Kernel 1: transpose caps_w [O][I][16 d][8 k] -> g_wT2 [i][k*8+d2][o] (u64 d-pairs)
// grid 4096 (one block per i), 256 threads.
// ---------------------------------------------------------------------------
__global__ __launch_bounds__(256) void transpose_w_kernel(const float* __restrict__ W)
{
    __shared__ float t[32 * 129];
    const int tid = threadIdx.x;
    const int i = blockIdx.x;
    for (int e = tid; e < 4096; e += 256) {
        int o = e >> 7, q = e & 127;
        t[o * 129 + q] = W[((size_t)o * ICAPS + i) * 128 + q];
    }
    __syncthreads();
    for (int e = tid; e < 2048; e += 256) {
        int k = e >> 8, d2 = (e >> 5) & 7, o = e & 31;
        float lo = t[o * 129 + (2 * d2) * 8 + k];       // q = d*8 + k
        float hi = t[o * 129 + (2 * d2 + 1) * 8 + k];
        g_wT2[(size_t)i * 2048 + e] = pack2(lo, hi);
    }
}

// ---------------------------------------------------------------------------
// Kernel 2: Conv3x3(SAME) + BN(eval) + ReLU + capsule squash -> g_pose
// grid (16, 64): x = 32-oc block, y = batch. 128 threads = 4 warps.
// warp = 8 consecutive oc (one capsule group!); lane = 2 adjacent positions.
// smem: padded img [8 ci][10][12] (zero halo) + weights [72][32].
// ---------------------------------------------------------------------------
__global__ __launch_bounds__(128, 5) void conv_pose_kernel(
    const float* __restrict__ x,
    const float* __restrict__ gamma, const float* __restrict__ beta,
    const float* __restrict__ mean, const float* __restrict__ var)
{
    __shared__ float img[960];    // [8 ci][10 r][12 c], halo = 0
    __shared__ float wts[2304];   // [ci*9+t][32 oc]

    const int tid  = threadIdx.x;
    const int og   = tid >> 5;        // warp 0..3 -> 8 oc
    const int lane = tid & 31;
    const int ocb  = blockIdx.x;      // 0..15
    const int b    = blockIdx.y;      // 0..63

    const int r  = lane >> 2;         // row 0..7
    const int c0 = (lane & 3) * 2;    // col pair base 0,2,4,6

    // zero padded image once (halo stays zero; interior overwritten per chunk)
    for (int e = tid; e < 960; e += 128) img[e] = 0.f;

    u64 acc[4][2];
#pragma unroll
    for (int p = 0; p < 4; p++) { acc[p][0] = 0ull; acc[p][1] = 0ull; }

    for (int cc = 0; cc < 64; cc++) {
        __syncthreads();
        for (int e = tid; e < 512; e += 128) {
            int ci = e >> 6, pos = e & 63;
            img[(ci * 10 + (pos >> 3) + 1) * 12 + (pos & 7) + 1] =
                x[(size_t)b * 32768 + cc * 512 + e];
        }
        for (int e = tid; e < 2304; e += 128)
            wts[e] = g_cwT[(size_t)(cc * 72 + (e >> 5)) * 512 + ocb * 32 + (e & 31)];
        __syncthreads();

#pragma unroll
        for (int ci = 0; ci < 8; ci++) {
            const float* ib = img + ci * 120 + r * 12 + c0;
            u64 xp[3][4];
#pragma unroll
            for (int dr = 0; dr < 3; dr++)
#pragma unroll
                for (int dc = 0; dc < 4; dc++) {
                    float v = ib[dr * 12 + dc];
                    xp[dr][dc] = pack2(v, v);
                }

            const float* wb = wts + ci * 288 + og * 8;
#pragma unroll
            for (int t = 0; t < 9; t++) {
                const ulonglong2 wa = *(const ulonglong2*)(wb + t * 32);      // oc 0..3
                const ulonglong2 wc = *(const ulonglong2*)(wb + t * 32 + 4);  // oc 4..7
                const int th = t / 3, tw = t % 3;
                fma2(acc[0][0], wa.x, xp[th][tw]);
                fma2(acc[0][1], wa.x, xp[th][tw + 1]);
                fma2(acc[1][0], wa.y, xp[th][tw]);
                fma2(acc[1][1], wa.y, xp[th][tw + 1]);
                fma2(acc[2][0], wc.x, xp[th][tw]);
                fma2(acc[2][1], wc.x, xp[th][tw + 1]);
                fma2(acc[3][0], wc.y, xp[th][tw]);
                fma2(acc[3][1], wc.y, xp[th][tw + 1]);
            }
        }
    }

    // epilogue: warp owns a full 8-oc capsule group -> in-register squash
    float scl[8], shf[8];
#pragma unroll
    for (int j = 0; j < 8; j++) {
        int oc = ocb * 32 + og * 8 + j;
        float inv = gamma[oc] * rsqrtf(var[oc] + 1e-5f);
        scl[j] = inv;
        shf[j] = beta[oc] - mean[oc] * inv;
    }
#pragma unroll
    for (int pc = 0; pc < 2; pc++) {
        int pos = r * 8 + c0 + pc;
        float y[8], ms = 0.f;
#pragma unroll
        for (int p = 0; p < 4; p++) {
            float2 f = unpack2(acc[p][pc]);
            float y0 = fmaxf(fmaf(f.x, scl[2 * p], shf[2 * p]), 0.f);
            float y1 = fmaxf(fmaf(f.y, scl[2 * p + 1], shf[2 * p + 1]), 0.f);
            y[2 * p] = y0; y[2 * p + 1] = y1;
            ms = fmaf(y0, y0, fmaf(y1, y1, ms));
        }
        float scale = ms / ((1.f + ms) * (sqrtf(ms) + 1e-8f));
        float* dst = g_pose + ((size_t)b * ICAPS + (ocb * 4 + og) * 64 + pos) * 8;
        ((float4*)dst)[0] = make_float4(y[0]*scale, y[1]*scale, y[2]*scale, y[3]*scale);
        ((float4*)dst)[1] = make_float4(y[4]*scale, y[5]*scale, y[6]*scale, y[7]*scale);
    }
}

// ---------------------------------------------------------------------------
// Kernel 3: routing pass, f32x2 d-pairs. lane = o; warp covers 16 i's x 8 b's.
// grid (32, 8). smem: pose 32KB + v2 16KB + sacc 128KB = 176KB.
// ---------------------------------------------------------------------------
#define ROUT_SMEM (45056 * 4)

template <bool UNIFORM>
__global__ __launch_bounds__(256, 1) void routing_kernel()
{
    extern __shared__ float rs[];
    float* pose_s = rs;                    // [8 b][128 i][8 k]      8192 f
    u64*   v2_s   = (u64*)(rs + 8192);     // [8 b][8 d2][32 o]     2048 u64
    u64*   sacc   = (u64*)(rs + 12288);    // [8 w][8 b][8 d2][32]  16384 u64

    const int tid   = threadIdx.x;
    const int warp  = tid >> 5;
    const int lane  = tid & 31;     // = o
    const int chunk = blockIdx.x;   // 0..31
    const int bg    = blockIdx.y;   // 0..7

    for (int e = tid; e < 16384; e += 256) sacc[e] = 0ull;
    for (int e = tid; e < 8192; e += 256) {
        int bb = e >> 10, r = e & 1023;
        pose_s[e] = g_pose[((size_t)(bg * 8 + bb) * ICAPS + chunk * 128) * 8 + r];
    }
    if (!UNIFORM) {
        for (int e = tid; e < 2048; e += 256) {
            int bb = e >> 8, d2 = (e >> 5) & 7, o = e & 31;
            v2_s[e] = pack2(g_va[bg * 4096 + (bb * 16 + 2 * d2) * 32 + o],
                            g_va[bg * 4096 + (bb * 16 + 2 * d2 + 1) * 32 + o]);
        }
    }
    __syncthreads();

#pragma unroll 1
    for (int t = 0; t < 16; t++) {
        const int li = t * 8 + warp;
        const int i  = chunk * 128 + li;
        const u64* wp = g_wT2 + (size_t)i * 2048 + lane;
        u64 wreg[64];                      // [k*8+d2]
#pragma unroll
        for (int q = 0; q < 64; q++) wreg[q] = __ldg(wp + q * 32);

#pragma unroll 1
        for (int bb = 0; bb < 8; bb++) {
            const float* pp = pose_s + (bb * 128 + li) * 8;
            u64 pk[8];
#pragma unroll
            for (int k = 0; k < 8; k++) pk[k] = pack2(pp[k], pp[k]);

            u64 xh2[8];
#pragma unroll
            for (int d2 = 0; d2 < 8; d2++) xh2[d2] = 0ull;
#pragma unroll
            for (int k = 0; k < 8; k++)
#pragma unroll
                for (int d2 = 0; d2 < 8; d2++)
                    fma2(xh2[d2], wreg[k * 8 + d2], pk[k]);

            float c;
            if (UNIFORM) {
                c = 0.03125f;
            } else {
                u64 lg2 = 0ull;
#pragma unroll
                for (int d2 = 0; d2 < 8; d2++)
                    fma2(lg2, v2_s[(bb * 8 + d2) * 32 + lane], xh2[d2]);
                float2 lf = unpack2(lg2);
                float lg = lf.x + lf.y;
                float mx = lg;
#pragma unroll
                for (int o2 = 16; o2 > 0; o2 >>= 1)
                    mx = fmaxf(mx, __shfl_xor_sync(0xffffffffu, mx, o2));
                float ex = __expf(lg - mx);
                float sm = ex;
#pragma unroll
                for (int o2 = 16; o2 > 0; o2 >>= 1)
                    sm += __shfl_xor_sync(0xffffffffu, sm, o2);
                c = ex / sm;
            }

            u64 c2 = pack2(c, c);
            u64* sb = sacc + warp * 2048 + bb * 256 + lane;
#pragma unroll
            for (int d2 = 0; d2 < 8; d2++) {
                u64 s = sb[d2 * 32];
                fma2(s, c2, xh2[d2]);
                sb[d2 * 32] = s;
            }
        }
    }

    __syncthreads();
    // reduce 8 warps, emit legacy float layout [bb][d][o]
    const float* sf = (const float*)sacc;
    for (int e = tid; e < 4096; e += 256) {
        int bb = e >> 9, d = (e >> 5) & 15, o = e & 31;
        int src = ((bb * 8 + (d >> 1)) * 32 + o) * 2 + (d & 1);
        float s = 0.f;
#pragma unroll
        for (int w = 0; w < 8; w++) s += sf[w * 4096 + src];
        g_spart[(size_t)chunk * 32768 + bg * 4096 + e] = s;
    }
}

// ---------------------------------------------------------------------------
// Kernel 4: fused chunk-reduce + squash. grid 64 (b), 512 threads (d,o).
// MODE 0: g_va = v0.  MODE 1: g_va += v1.  MODE 2: g_out = v2.
// ---------------------------------------------------------------------------
template <int MODE>
__global__ __launch_bounds__(512) void reduce_squash_kernel()
{
    __shared__ float sq[512];
    __shared__ float colsum[32];
    const int b = blockIdx.x;
    const int o = threadIdx.x & 31;
    const int e = b * 512 + threadIdx.x;
    float s = 0.f;
#pragma unroll
    for (int c = 0; c < 32; c++) s += g_spart[(size_t)c * 32768 + e];
    sq[threadIdx.x] = s * s;
    __syncthreads();
    if (threadIdx.x < 32) {
        float m = 0.f;
#pragma unroll
        for (int dd = 0; dd < 16; dd++) m += sq[dd * 32 + threadIdx.x];
        colsum[threadIdx.x] = m;
    }
    __syncthreads();
    float ms = colsum[o];
    float v = s * (ms / ((1.f + ms) * (sqrtf(ms) + 1e-8f)));
    if (MODE == 0) g_va[e] = v;
    else if (MODE == 1) g_va[e] += v;
    else g_out[e] = v;
}

// ---------------------------------------------------------------------------
// Kernel 5: VAE head
// ---------------------------------------------------------------------------
__global__ __launch_bounds__(256) void head_kernel(
    const float* __restrict__ W1, const float* __restrict__ B1,
    const float* __restrict__ W2, const float* __restrict__ B2,
    const float* __restrict__ Wv, const float* __restrict__ Bv,
    float* __restrict__ out)
{
    __shared__ float ov[8][16];
    __shared__ float hb[8][1024];
    const int tid = threadIdx.x;
    const int pid0 = blockIdx.x * 8;

    if (tid < 128) {
        int pr = tid >> 4, d = tid & 15;
        int pid = pid0 + pr, b = pid >> 5, o = pid & 31;
        ov[pr][d] = g_out[(b * 16 + d) * 32 + o];
    }
    __syncthreads();

    for (int idx = tid; idx < 8192; idx += 256) {
        int pr = idx >> 10, j = idx & 1023;
        float a = B1[j];
#pragma unroll
        for (int k = 0; k < 16; k++)
            a = fmaf(ov[pr][k], W1[k * 1024 + j], a);
        hb[pr][j] = fmaxf(a, 0.f);
    }
    __syncthreads();

#pragma unroll 1
    for (int rep = 0; rep < 2; rep++) {
        int dotid = rep * 256 + tid;
        int pr = dotid >> 6, c = dotid & 63;
        float a = B2[c];
#pragma unroll 8
        for (int j = 0; j < 1024; j++)
            a = fmaf(hb[pr][j], W2[j * 64 + c], a);
        int pid = pid0 + pr;
        out[pid * 64 + c] = a;
        out[131072 + pid * 64 + c] = a;

        float av = Bv[c];
#pragma unroll
        for (int k = 0; k < 16; k++)
            av = fmaf(ov[pr][k], Wv[k * 64 + c], av);
        float sp = fmaxf(av, 0.f) + log1pf(expf(-fabsf(av)));
        out[262144 + pid * 64 + c] = sp + 1e-8f;
    }
}

// ---------------------------------------------------------------------------
// Launch
// ---------------------------------------------------------------------------
extern "C" void kernel_launch(void* const* d_in, const int* in_sizes, int n_in,
                              void* d_out, int out_size)
{
    (void)in_sizes; (void)n_in; (void)out_size;
    const float* x      = (const float*)d_in[0];
    const float* conv_w = (const float*)d_in[1];
    const float* gam    = (const float*)d_in[2];
    const float* bet    = (const float*)d_in[3];
    const float* mu     = (const float*)d_in[4];
    const float* var    = (const float*)d_in[5];
    const float* capw   = (const float*)d_in[6];
    const float* w1     = (const float*)d_in[7];
    const float* b1     = (const float*)d_in[8];
    const float* w2     = (const float*)d_in[9];
    const float* b2     = (const float*)d_in[10];
    const float* wv     = (const float*)d_in[11];
    const float* bv     = (const float*)d_in[12];
    float* out = (float*)d_out;

    cudaFuncSetAttribute(routing_kernel<true>,
                         cudaFuncAttributeMaxDynamicSharedMemorySize, ROUT_SMEM);
    cudaFuncSetAttribute(routing_kernel<false>,
                         cudaFuncAttributeMaxDynamicSharedMemorySize, ROUT_SMEM);

    transpose_cw_kernel<<<dim3(144, 16), 256>>>(conv_w);                 // 0
    transpose_w_kernel<<<4096, 256>>>(capw);                             // 1
    conv_pose_kernel<<<dim3(16, 64), 128>>>(x, gam, bet, mu, var);       // 2
    routing_kernel<true><<<dim3(32, 8), 256, ROUT_SMEM>>>();             // 3 <- profiled slot
    reduce_squash_kernel<0><<<64, 512>>>();
    routing_kernel<false><<<dim3(32, 8), 256, ROUT_SMEM>>>();
    reduce_squash_kernel<1><<<64, 512>>>();
    routing_kernel<false><<<dim3(32, 8), 256, ROUT_SMEM>>>();
    reduce_squash_kernel<2><<<64, 512>>>();
    head_kernel<<<256, 256>>>(w1, b1, w2, b2, wv, bv, out);
}